// round 13
// baseline (speedup 1.0000x reference)
#include <cuda_runtime.h>
#include <cuda_bf16.h>
#include <cstdint>

// ---------------------------------------------------------------------------
// DeepTransitionRNN: T=512, B=128, D=256, H=256, L=4
//
//  1) memset(out), memset(g_Hbuf: tags -> 0)
//  2) xproj_kernel: XP[t][m][hc][b] = x[t,b,:] @ Wm[:,hc]  (5 x-side mats)
//  3) rnn_kernel: persistent, 128 CTAs = 4 groups (32 batch rows) x 32 CTAs
//     (8 H-columns each). 16 h-side weight slices SMEM-resident (128KB).
//     5 GEMM phases/step. Self-synchronizing h exchange: each h element is an
//     atomic 8B {f32 val, u32 tag} in a 2-deep ping-pong ring; consumers poll
//     the data words themselves. R13: ONE __syncthreads per phase -- the
//     partials buffer Gp is ping-ponged (bank = phase parity) so the post-ew
//     barrier is gone and each warp publishes then immediately polls its next
//     k-slice.
// ---------------------------------------------------------------------------

#define T_STEPS 512
#define BATCH   128
#define DDIM    256
#define HDIM    256
#define NLAYERS 4
#define NMAT    16
#define GROUPS  4
#define RPG     32          // batch rows per group
#define CPC     8           // H columns per CTA
#define CPG     32          // CTAs per group
#define XP_MS   (HDIM*BATCH)
#define GPBANK  8192        // floats per Gp bank (8 warps x 4 mats x 256)

typedef unsigned long long ull;

// ---- device scratch (static globals: allocation-free) ----------------------
__device__ __align__(16) float g_XP[(size_t)T_STEPS * 5 * HDIM * BATCH];
__device__ __align__(16) ull   g_Hbuf[2][GROUPS][HDIM * RPG];  // {val, tag}

// ---- activations (fp32, error ~1e-7) ---------------------------------------
__device__ __forceinline__ float sigmoidf_(float x) {
    x = fminf(fmaxf(x, -30.f), 30.f);
    return 1.f / (1.f + __expf(-x));
}
__device__ __forceinline__ float tanhf_(float x) {
    x = fminf(fmaxf(x, -15.f), 15.f);
    float e = __expf(2.f * x);
    return (e - 1.f) / (e + 1.f);
}

#define FMA2(acc, a, b) \
    asm("fma.rn.f32x2 %0,%1,%2,%0;" : "+l"(acc) : "l"(a), "l"(b))
#define PACK2(d, s) \
    asm("mov.b64 %0,{%1,%1};" : "=l"(d) : "f"(s))
#define UNPK(s, lo, hi) \
    asm("mov.b64 {%0,%1},%2;" : "=f"(lo), "=f"(hi) : "l"(s))

__device__ __forceinline__ ull ld_rlx64(const ull* p) {
    ull v;
    asm volatile("ld.relaxed.gpu.global.b64 %0,[%1];"
                 : "=l"(v) : "l"(p) : "memory");
    return v;
}
__device__ __forceinline__ void st_rlx64(ull* p, ull v) {
    asm volatile("st.relaxed.gpu.global.b64 [%0],%1;"
                 :: "l"(p), "l"(v) : "memory");
}

// ---------------------------------------------------------------------------
// Kernel 1: x-projection GEMM (validated R7-R12, unchanged).
// ---------------------------------------------------------------------------
__global__ void __launch_bounds__(256) xproj_kernel(
    const float* __restrict__ x,
    const float* __restrict__ Wr, const float* __restrict__ Wz,
    const float* __restrict__ Wl, const float* __restrict__ Cx,
    const float* __restrict__ Wt)
{
    __shared__ float AsmT[16 * 68];
    __shared__ float Bsm [16 * 68];
    __shared__ float Csm [64 * 68];

    const int tid   = threadIdx.x;
    const int bn    = blockIdx.x;
    const int bm    = blockIdx.y;
    const int t     = bm >> 1;
    const int brow0 = (bm & 1) * 64;
    const int n0    = bn * 64;
    const int mat   = n0 >> 8;
    const int hc0   = n0 & 255;
    const float* Wsrc = (mat == 0) ? Wr : (mat == 1) ? Wz :
                        (mat == 2) ? Wl : (mat == 3) ? Cx : Wt;

    const int ty = tid >> 4;
    const int tx = tid & 15;

    ull acc[4][2];
    #pragma unroll
    for (int i = 0; i < 4; ++i) { acc[i][0] = 0ull; acc[i][1] = 0ull; }

    const int a_m = tid >> 2;
    const int a_k = (tid & 3) * 4;
    const int b_k = tid >> 4;
    const int b_c = (tid & 15) * 4;

    const float* ag = x + ((size_t)(t * BATCH + brow0 + a_m)) * DDIM + a_k;
    const float* bg = Wsrc + (size_t)b_k * HDIM + hc0 + b_c;

    for (int k0 = 0; k0 < DDIM; k0 += 16) {
        float4 av = *(const float4*)(ag + k0);
        AsmT[(a_k + 0) * 68 + a_m] = av.x;
        AsmT[(a_k + 1) * 68 + a_m] = av.y;
        AsmT[(a_k + 2) * 68 + a_m] = av.z;
        AsmT[(a_k + 3) * 68 + a_m] = av.w;
        float4 bv = *(const float4*)(bg + (size_t)k0 * HDIM);
        *(float4*)&Bsm[b_k * 68 + b_c] = bv;
        __syncthreads();

        #pragma unroll
        for (int k = 0; k < 16; ++k) {
            float4 a4 = *(const float4*)&AsmT[k * 68 + ty * 4];
            ulonglong2 wv = *(const ulonglong2*)&Bsm[k * 68 + tx * 4];
            ull a2;
            #define XPROJ_STEP(i, comp)                                          \
                PACK2(a2, comp);                                                 \
                FMA2(acc[i][0], a2, wv.x);                                       \
                FMA2(acc[i][1], a2, wv.y);
            XPROJ_STEP(0, a4.x)
            XPROJ_STEP(1, a4.y)
            XPROJ_STEP(2, a4.z)
            XPROJ_STEP(3, a4.w)
            #undef XPROJ_STEP
        }
        __syncthreads();
    }

    #pragma unroll
    for (int i = 0; i < 4; ++i) {
        float c0, c1, c2, c3;
        UNPK(acc[i][0], c0, c1);
        UNPK(acc[i][1], c2, c3);
        Csm[(tx * 4 + 0) * 68 + ty * 4 + i] = c0;
        Csm[(tx * 4 + 1) * 68 + ty * 4 + i] = c1;
        Csm[(tx * 4 + 2) * 68 + ty * 4 + i] = c2;
        Csm[(tx * 4 + 3) * 68 + ty * 4 + i] = c3;
    }
    __syncthreads();

    const int nl = tid >> 2;
    const int mq = tid & 3;
    float* dst = g_XP + ((size_t)((t * 5 + mat) * HDIM + hc0 + nl)) * BATCH
                 + brow0 + mq * 16;
    #pragma unroll
    for (int q = 0; q < 4; ++q) {
        float4 v = *(const float4*)&Csm[nl * 68 + mq * 16 + q * 4];
        *(float4*)(dst + q * 4) = v;
    }
}

// ---------------------------------------------------------------------------
// Tagged-stream GEMM: NM matrices x 8 cols x 32 rows over warp w's 32-k slice.
// h elements are {val, tag} pairs; the warp polls its own chunk's tags (data =
// readiness), double-buffered in chunks of 8 k.
// ---------------------------------------------------------------------------
template <int NM>
__device__ __forceinline__ void gemm_warp(
    const ull*  __restrict__ hb,      // tagged h buffer (read side of ring)
    const float* __restrict__ wbase,  // Wsm + first-matrix offset
    float* __restrict__ GpW,          // partials bank: [w][mat][col*32+row]
    int w, int lane, unsigned tag)
{
    ull acc[NM * 4];
    #pragma unroll
    for (int i = 0; i < NM * 4; ++i) acc[i] = 0ull;

    const ull* hp = hb + (w << 10) + lane;     // element (k = w*32 + i, row=lane)
    const float* wk = wbase + (w * 32) * 8;    // weights for this k-slice

    ull d0[8], d1[8];

    // chunk 0: poll until every lane's 8 tags match
    for (;;) {
        #pragma unroll
        for (int i = 0; i < 8; ++i) d0[i] = ld_rlx64(hp + i * 32);
        bool ok = true;
        #pragma unroll
        for (int i = 0; i < 8; ++i) ok &= ((unsigned)(d0[i] >> 32) == tag);
        if (__ballot_sync(0xffffffffu, ok) == 0xffffffffu) break;
    }

    #pragma unroll
    for (int c = 0; c < 4; ++c) {
        // prefetch next chunk while computing this one
        if (c < 3) {
            #pragma unroll
            for (int i = 0; i < 8; ++i)
                d1[i] = ld_rlx64(hp + ((c + 1) * 8 + i) * 32);
        }
        #pragma unroll
        for (int i = 0; i < 8; ++i) {
            float h = __uint_as_float((unsigned)d0[i]);
            ull hd; PACK2(hd, h);
            #pragma unroll
            for (int m = 0; m < NM; ++m) {
                const float* q = wk + m * 2048 + (c * 8 + i) * 8;
                ulonglong2 wa = *(const ulonglong2*)q;
                ulonglong2 wb = *(const ulonglong2*)(q + 4);
                FMA2(acc[m*4+0], hd, wa.x); FMA2(acc[m*4+1], hd, wa.y);
                FMA2(acc[m*4+2], hd, wb.x); FMA2(acc[m*4+3], hd, wb.y);
            }
        }
        if (c < 3) {
            // verify prefetched chunk; reload until tags match
            for (;;) {
                bool ok = true;
                #pragma unroll
                for (int i = 0; i < 8; ++i)
                    ok &= ((unsigned)(d1[i] >> 32) == tag);
                if (__ballot_sync(0xffffffffu, ok) == 0xffffffffu) break;
                #pragma unroll
                for (int i = 0; i < 8; ++i)
                    d1[i] = ld_rlx64(hp + ((c + 1) * 8 + i) * 32);
            }
            #pragma unroll
            for (int i = 0; i < 8; ++i) d0[i] = d1[i];
        }
    }

    float* gp = GpW + (w * 4) * 256 + lane;
    #pragma unroll
    for (int m = 0; m < NM; ++m) {
        #pragma unroll
        for (int cp = 0; cp < 4; ++cp) {
            float lo, hi;
            UNPK(acc[m*4+cp], lo, hi);
            gp[m*256 + (2*cp)   * 32] = lo;
            gp[m*256 + (2*cp+1) * 32] = hi;
        }
    }
}

// ---------------------------------------------------------------------------
// Kernel 2: the recurrence. 128 CTAs x 256 threads, persistent.
// Dynamic smem: Wsm 16x256x8 (128KB) | Gp 2 banks x 8(w) x 4(mat) x 256 (64KB)
// One __syncthreads per phase; Gp bank = phase parity.
// ---------------------------------------------------------------------------
#define SMEM_FLOATS (NMAT*HDIM*CPC + 2*GPBANK)
#define SMEM_BYTES  (SMEM_FLOATS * 4)

__global__ void __launch_bounds__(256, 1) rnn_kernel(
    const float* __restrict__ Wr, const float* __restrict__ Wz,
    const float* __restrict__ Wl, const float* __restrict__ Ch,
    const float* __restrict__ Tr, const float* __restrict__ Tz,
    const float* __restrict__ Tn,
    const int*   __restrict__ lengths,
    float*       __restrict__ out)
{
    extern __shared__ float smem[];
    float* Wsm = smem;                       // 32768 floats
    float* Gp  = smem + NMAT * HDIM * CPC;   //  2 x 8192 floats

    const int tid  = threadIdx.x;
    const int cta  = blockIdx.x;
    const int g    = cta >> 5;
    const int cb   = cta & 31;
    const int col0 = cb * CPC;

    // ---- load this CTA's 8-column slice of all 16 h-side matrices ----------
    for (int idx = tid; idx < NMAT * HDIM * CPC; idx += 256) {
        int m = idx >> 11;
        int k = (idx >> 3) & 255;
        int c = idx & 7;
        const float* src;
        if (m == 0)      src = Wr + (size_t)(DDIM + k) * HDIM;
        else if (m == 1) src = Wz + (size_t)(DDIM + k) * HDIM;
        else if (m == 2) src = Wl + (size_t)(DDIM + k) * HDIM;
        else if (m == 3) src = Ch + (size_t)k * HDIM;
        else {
            int mm = m - 4, layer = mm / 3, which = mm % 3;
            const float* base = (which == 0) ? Tr : (which == 1) ? Tz : Tn;
            src = base + (size_t)layer * HDIM * HDIM + (size_t)k * HDIM;
        }
        Wsm[idx] = src[col0 + c];
    }
    __syncthreads();

    const int r     = tid & 31;       // batch row within group (also GEMM lane)
    const int cl    = tid >> 5;       // local column (also GEMM warp id)
    const int b     = g * RPG + r;
    const int colg  = col0 + cl;
    const int mylen = lengths[b];
    const int Lg    = lengths[g * RPG];   // sorted descending -> group max

    const int w    = cl;              // warp id
    const int lane = r;

    unsigned p = 0;                   // global phase counter (tag base)
    ull* buf0 = &g_Hbuf[0][g][0];     // tags memset to 0 each launch
    ull* buf1 = &g_Hbuf[1][g][0];

    const int hidx = colg * 32 + r;   // this thread's h element index
    float hown = 0.f;

    for (int t = 0; t < Lg; ++t) {
        const bool act = (t < mylen);
        const float hstep = hown;

        // prefetch this step's x-projections (hidden under phase-A poll/GEMM)
        const float* xp = g_XP + ((size_t)(t * 5) * HDIM + colg) * BATCH + b;
        float xr = __ldcg(xp + 0 * XP_MS);
        float xz = __ldcg(xp + 1 * XP_MS);
        float xl = __ldcg(xp + 2 * XP_MS);
        float xc = __ldcg(xp + 3 * XP_MS);
        float xw = __ldcg(xp + 4 * XP_MS);

        // ================= phase A: 4 GEMMs, warp = k-slice ==================
        {
            const ull* rbuf  = (p & 1) ? buf1 : buf0;
            float*     bank  = Gp + (p & 1) * GPBANK;
            gemm_warp<4>(rbuf, Wsm, bank, w, lane, p);
            __syncthreads();   // the ONLY barrier of this phase

            float gr = 0.f, gz = 0.f, gl = 0.f, gch = 0.f;
            #pragma unroll
            for (int ww = 0; ww < 8; ++ww) {
                const float* q = bank + ww * 1024 + tid;
                gr += q[0]; gz += q[256]; gl += q[512]; gch += q[768];
            }
            float rv = sigmoidf_(xr + gr);
            float zv = sigmoidf_(xz + gz);
            float lv = sigmoidf_(xl + gl);
            float nv = tanhf_(xc + rv * gch) + lv * xw;
            hown = (1.f - zv) * hown + zv * nv;
            ull pk;
            asm("mov.b64 %0,{%1,%2};" : "=l"(pk)
                : "r"(__float_as_uint(hown)), "r"(p + 1));
            st_rlx64(((p & 1) ? buf0 : buf1) + hidx, pk);   // publish, then GO
        }
        ++p;

        // ================= 4 transition layers (Tr,Tz,Tn) ===================
        #pragma unroll 1
        for (int layer = 0; layer < NLAYERS; ++layer) {
            const ull* rbuf = (p & 1) ? buf1 : buf0;
            float*     bank = Gp + (p & 1) * GPBANK;
            gemm_warp<3>(rbuf, Wsm + (4 + 3 * layer) * 2048, bank, w, lane, p);
            __syncthreads();   // the ONLY barrier of this phase

            float grr = 0.f, gzz = 0.f, gnn = 0.f;
            #pragma unroll
            for (int ww = 0; ww < 8; ++ww) {
                const float* q = bank + ww * 1024 + tid;
                grr += q[0]; gzz += q[256]; gnn += q[512];
            }
            float rr = sigmoidf_(grr);
            float zz = sigmoidf_(gzz);
            float nn = tanhf_(rr * gnn);
            float hnew = (1.f - zz) * nn + zz * hown;

            float outval = 0.f;
            bool  dostore = false;
            if (layer == NLAYERS - 1) {
                hown = act ? hnew : hstep;
                outval  = hnew;
                dostore = act;
            } else {
                hown = hnew;
            }
            ull pk;
            asm("mov.b64 %0,{%1,%2};" : "=l"(pk)
                : "r"(__float_as_uint(hown)), "r"(p + 1));
            st_rlx64(((p & 1) ? buf0 : buf1) + hidx, pk);   // publish first
            ++p;
            if (dostore)   // off the critical path
                out[((size_t)t * BATCH + b) * HDIM + colg] = outval;
        }
    }
}

// ---------------------------------------------------------------------------
// kernel_launch: memsets -> x-projection GEMM -> persistent recurrence
// ---------------------------------------------------------------------------
extern "C" void kernel_launch(void* const* d_in, const int* in_sizes, int n_in,
                              void* d_out, int out_size)
{
    const float* x       = (const float*)d_in[0];
    const int*   lengths = (const int*)  d_in[1];
    const float* Wr      = (const float*)d_in[2];
    const float* Wz      = (const float*)d_in[3];
    const float* Wl      = (const float*)d_in[4];
    const float* Wt      = (const float*)d_in[5];
    const float* Cx      = (const float*)d_in[6];
    const float* Ch      = (const float*)d_in[7];
    const float* Tr      = (const float*)d_in[8];
    const float* Tz      = (const float*)d_in[9];
    const float* Tn      = (const float*)d_in[10];
    float* out = (float*)d_out;
    (void)in_sizes; (void)n_in;

    cudaMemsetAsync(out, 0, (size_t)out_size * sizeof(float));

    // Ring buffer must start with {0.0f, tag=0} every launch: tag 0 == the
    // initial h the first GEMM (phase 0) waits for. Graph-replay safe.
    void* hb_ptr = nullptr;
    cudaGetSymbolAddress(&hb_ptr, g_Hbuf);
    cudaMemsetAsync(hb_ptr, 0, sizeof(ull) * 2 * GROUPS * HDIM * RPG);

    dim3 ggrid(20, 1024);
    xproj_kernel<<<ggrid, 256>>>(x, Wr, Wz, Wl, Cx, Wt);

    cudaFuncSetAttribute(rnn_kernel,
                         cudaFuncAttributeMaxDynamicSharedMemorySize,
                         SMEM_BYTES);
    rnn_kernel<<<GROUPS * CPG, 256, SMEM_BYTES>>>(
        Wr, Wz, Wl, Ch, Tr, Tz, Tn, lengths, out);
}

// round 14
// speedup vs baseline: 1.1959x; 1.1959x over previous
#include <cuda_runtime.h>
#include <cuda_bf16.h>
#include <cstdint>

// ---------------------------------------------------------------------------
// DeepTransitionRNN: T=512, B=128, D=256, H=256, L=4
//
//  1) memset(out), memset(g_Hbuf: tags -> 0)
//  2) xproj_kernel: XP[t][m][hc][b] = x[t,b,:] @ Wm[:,hc]  (5 x-side mats)
//  3) rnn_kernel: persistent, 256 CTAs = 4 groups (32 batch rows) x 64 CTAs
//     (4 H-columns each), TWO CTAs resident per SM (__launch_bounds__(256,2))
//     so co-resident CTAs from different groups hide each other's
//     publish/discovery latency. 16 h-side weight slices SMEM-resident (64KB).
//     Self-synchronizing h exchange: 8B {f32 val, u32 tag} ring, consumers
//     poll the data words. Warps 0-3 run the epilogue (reduce+ew+publish);
//     warps 4-7 go straight from the sync into next-phase polling.
// ---------------------------------------------------------------------------

#define T_STEPS 512
#define BATCH   128
#define DDIM    256
#define HDIM    256
#define NLAYERS 4
#define NMAT    16
#define GROUPS  4
#define RPG     32          // batch rows per group
#define CPC     4           // H columns per CTA
#define CPG     64          // CTAs per group
#define XP_MS   (HDIM*BATCH)
#define GPBANK  (8*4*128)   // floats per partials bank (8 warps x 4 mats x 128)
#define WSM_F   (NMAT*HDIM*CPC)   // 16384 floats = 64KB

typedef unsigned long long ull;

// ---- device scratch (static globals: allocation-free) ----------------------
__device__ __align__(16) float g_XP[(size_t)T_STEPS * 5 * HDIM * BATCH];
__device__ __align__(16) ull   g_Hbuf[2][GROUPS][HDIM * RPG];  // {val, tag}

// ---- activations (fp32, error ~1e-7) ---------------------------------------
__device__ __forceinline__ float sigmoidf_(float x) {
    x = fminf(fmaxf(x, -30.f), 30.f);
    return 1.f / (1.f + __expf(-x));
}
__device__ __forceinline__ float tanhf_(float x) {
    x = fminf(fmaxf(x, -15.f), 15.f);
    float e = __expf(2.f * x);
    return (e - 1.f) / (e + 1.f);
}

#define FMA2(acc, a, b) \
    asm("fma.rn.f32x2 %0,%1,%2,%0;" : "+l"(acc) : "l"(a), "l"(b))
#define PACK2(d, s) \
    asm("mov.b64 %0,{%1,%1};" : "=l"(d) : "f"(s))
#define UNPK(s, lo, hi) \
    asm("mov.b64 {%0,%1},%2;" : "=f"(lo), "=f"(hi) : "l"(s))

__device__ __forceinline__ ull ld_rlx64(const ull* p) {
    ull v;
    asm volatile("ld.relaxed.gpu.global.b64 %0,[%1];"
                 : "=l"(v) : "l"(p) : "memory");
    return v;
}
__device__ __forceinline__ void st_rlx64(ull* p, ull v) {
    asm volatile("st.relaxed.gpu.global.b64 [%0],%1;"
                 :: "l"(p), "l"(v) : "memory");
}

// ---------------------------------------------------------------------------
// Kernel 1: x-projection GEMM (validated R7-R13, unchanged).
// ---------------------------------------------------------------------------
__global__ void __launch_bounds__(256) xproj_kernel(
    const float* __restrict__ x,
    const float* __restrict__ Wr, const float* __restrict__ Wz,
    const float* __restrict__ Wl, const float* __restrict__ Cx,
    const float* __restrict__ Wt)
{
    __shared__ float AsmT[16 * 68];
    __shared__ float Bsm [16 * 68];
    __shared__ float Csm [64 * 68];

    const int tid   = threadIdx.x;
    const int bn    = blockIdx.x;
    const int bm    = blockIdx.y;
    const int t     = bm >> 1;
    const int brow0 = (bm & 1) * 64;
    const int n0    = bn * 64;
    const int mat   = n0 >> 8;
    const int hc0   = n0 & 255;
    const float* Wsrc = (mat == 0) ? Wr : (mat == 1) ? Wz :
                        (mat == 2) ? Wl : (mat == 3) ? Cx : Wt;

    const int ty = tid >> 4;
    const int tx = tid & 15;

    ull acc[4][2];
    #pragma unroll
    for (int i = 0; i < 4; ++i) { acc[i][0] = 0ull; acc[i][1] = 0ull; }

    const int a_m = tid >> 2;
    const int a_k = (tid & 3) * 4;
    const int b_k = tid >> 4;
    const int b_c = (tid & 15) * 4;

    const float* ag = x + ((size_t)(t * BATCH + brow0 + a_m)) * DDIM + a_k;
    const float* bg = Wsrc + (size_t)b_k * HDIM + hc0 + b_c;

    for (int k0 = 0; k0 < DDIM; k0 += 16) {
        float4 av = *(const float4*)(ag + k0);
        AsmT[(a_k + 0) * 68 + a_m] = av.x;
        AsmT[(a_k + 1) * 68 + a_m] = av.y;
        AsmT[(a_k + 2) * 68 + a_m] = av.z;
        AsmT[(a_k + 3) * 68 + a_m] = av.w;
        float4 bv = *(const float4*)(bg + (size_t)k0 * HDIM);
        *(float4*)&Bsm[b_k * 68 + b_c] = bv;
        __syncthreads();

        #pragma unroll
        for (int k = 0; k < 16; ++k) {
            float4 a4 = *(const float4*)&AsmT[k * 68 + ty * 4];
            ulonglong2 wv = *(const ulonglong2*)&Bsm[k * 68 + tx * 4];
            ull a2;
            #define XPROJ_STEP(i, comp)                                          \
                PACK2(a2, comp);                                                 \
                FMA2(acc[i][0], a2, wv.x);                                       \
                FMA2(acc[i][1], a2, wv.y);
            XPROJ_STEP(0, a4.x)
            XPROJ_STEP(1, a4.y)
            XPROJ_STEP(2, a4.z)
            XPROJ_STEP(3, a4.w)
            #undef XPROJ_STEP
        }
        __syncthreads();
    }

    #pragma unroll
    for (int i = 0; i < 4; ++i) {
        float c0, c1, c2, c3;
        UNPK(acc[i][0], c0, c1);
        UNPK(acc[i][1], c2, c3);
        Csm[(tx * 4 + 0) * 68 + ty * 4 + i] = c0;
        Csm[(tx * 4 + 1) * 68 + ty * 4 + i] = c1;
        Csm[(tx * 4 + 2) * 68 + ty * 4 + i] = c2;
        Csm[(tx * 4 + 3) * 68 + ty * 4 + i] = c3;
    }
    __syncthreads();

    const int nl = tid >> 2;
    const int mq = tid & 3;
    float* dst = g_XP + ((size_t)((t * 5 + mat) * HDIM + hc0 + nl)) * BATCH
                 + brow0 + mq * 16;
    #pragma unroll
    for (int q = 0; q < 4; ++q) {
        float4 v = *(const float4*)&Csm[nl * 68 + mq * 16 + q * 4];
        *(float4*)(dst + q * 4) = v;
    }
}

// ---------------------------------------------------------------------------
// Tagged-stream GEMM: NM matrices x 4 cols x 32 rows over warp w's 32-k slice.
// h elements are {val, tag} pairs; warp polls its own chunk's tags, chunks of
// 8 k, double-buffered.
// ---------------------------------------------------------------------------
template <int NM>
__device__ __forceinline__ void gemm_warp(
    const ull*  __restrict__ hb,      // tagged h buffer (read side of ring)
    const float* __restrict__ wbase,  // Wsm + first-matrix offset (mat stride 1024)
    float* __restrict__ bank,         // partials bank: [w][mat][elem(128)]
    int w, int lane, unsigned tag)
{
    ull acc[NM * 2];
    #pragma unroll
    for (int i = 0; i < NM * 2; ++i) acc[i] = 0ull;

    const ull* hp = hb + (w << 10) + lane;     // k = w*32 + i, row = lane
    const float* wk = wbase + w * 128;         // (w*32)*CPC floats

    ull d0[8], d1[8];

    // chunk 0: poll until every lane's 8 tags match
    for (;;) {
        #pragma unroll
        for (int i = 0; i < 8; ++i) d0[i] = ld_rlx64(hp + i * 32);
        bool ok = true;
        #pragma unroll
        for (int i = 0; i < 8; ++i) ok &= ((unsigned)(d0[i] >> 32) == tag);
        if (__ballot_sync(0xffffffffu, ok) == 0xffffffffu) break;
    }

    #pragma unroll
    for (int c = 0; c < 4; ++c) {
        if (c < 3) {
            #pragma unroll
            for (int i = 0; i < 8; ++i)
                d1[i] = ld_rlx64(hp + ((c + 1) * 8 + i) * 32);
        }
        #pragma unroll
        for (int i = 0; i < 8; ++i) {
            float h = __uint_as_float((unsigned)d0[i]);
            ull hd; PACK2(hd, h);
            #pragma unroll
            for (int m = 0; m < NM; ++m) {
                const ulonglong2 wv =
                    *(const ulonglong2*)(wk + m * 1024 + (c * 8 + i) * 4);
                FMA2(acc[m*2+0], hd, wv.x);
                FMA2(acc[m*2+1], hd, wv.y);
            }
        }
        if (c < 3) {
            for (;;) {
                bool ok = true;
                #pragma unroll
                for (int i = 0; i < 8; ++i)
                    ok &= ((unsigned)(d1[i] >> 32) == tag);
                if (__ballot_sync(0xffffffffu, ok) == 0xffffffffu) break;
                #pragma unroll
                for (int i = 0; i < 8; ++i)
                    d1[i] = ld_rlx64(hp + ((c + 1) * 8 + i) * 32);
            }
            #pragma unroll
            for (int i = 0; i < 8; ++i) d0[i] = d1[i];
        }
    }

    float* gp = bank + (w * 4) * 128 + lane;   // mat stride 128 elems
    #pragma unroll
    for (int m = 0; m < NM; ++m) {
        #pragma unroll
        for (int cp = 0; cp < 2; ++cp) {
            float lo, hi;
            UNPK(acc[m*2+cp], lo, hi);
            gp[m*128 + (2*cp)   * 32] = lo;
            gp[m*128 + (2*cp+1) * 32] = hi;
        }
    }
}

// ---------------------------------------------------------------------------
// Kernel 2: the recurrence. 256 CTAs x 256 threads, 2 CTAs per SM.
// Dynamic smem: Wsm 16x256x4 (64KB) | Gp 2 banks x 8(w) x 4(mat) x 128 (32KB)
// ---------------------------------------------------------------------------
#define SMEM_FLOATS (WSM_F + 2*GPBANK)
#define SMEM_BYTES  (SMEM_FLOATS * 4)

__global__ void __launch_bounds__(256, 2) rnn_kernel(
    const float* __restrict__ Wr, const float* __restrict__ Wz,
    const float* __restrict__ Wl, const float* __restrict__ Ch,
    const float* __restrict__ Tr, const float* __restrict__ Tz,
    const float* __restrict__ Tn,
    const int*   __restrict__ lengths,
    float*       __restrict__ out)
{
    extern __shared__ float smem[];
    float* Wsm = smem;                 // 16384 floats
    float* Gp  = smem + WSM_F;         // 2 x 4096 floats

    const int tid  = threadIdx.x;
    const int cta  = blockIdx.x;
    const int g    = cta >> 6;         // group 0..3
    const int cb   = cta & 63;         // column block within group
    const int col0 = cb * CPC;

    // ---- load this CTA's 4-column slice of all 16 h-side matrices ----------
    for (int idx = tid; idx < WSM_F; idx += 256) {
        int m = idx >> 10;
        int k = (idx >> 2) & 255;
        int c = idx & 3;
        const float* src;
        if (m == 0)      src = Wr + (size_t)(DDIM + k) * HDIM;
        else if (m == 1) src = Wz + (size_t)(DDIM + k) * HDIM;
        else if (m == 2) src = Wl + (size_t)(DDIM + k) * HDIM;
        else if (m == 3) src = Ch + (size_t)k * HDIM;
        else {
            int mm = m - 4, layer = mm / 3, which = mm % 3;
            const float* base = (which == 0) ? Tr : (which == 1) ? Tz : Tn;
            src = base + (size_t)layer * HDIM * HDIM + (size_t)k * HDIM;
        }
        Wsm[idx] = src[col0 + c];
    }
    __syncthreads();

    const int r     = tid & 31;        // row (epilogue) / GEMM lane
    const int cl    = tid >> 5;        // warp id; epilogue col for tid<128
    const int b     = g * RPG + r;
    const int colg  = col0 + cl;       // valid for tid<128 (cl<4)
    const int mylen = lengths[b];
    const int Lg    = lengths[g * RPG];    // sorted descending -> group max

    const int w    = cl;               // GEMM warp id
    const int lane = r;
    const bool epi = (tid < 128);      // epilogue threads (warps 0-3)

    unsigned p = 0;                    // global phase counter (tag base)
    ull* buf0 = &g_Hbuf[0][g][0];      // tags memset to 0 each launch
    ull* buf1 = &g_Hbuf[1][g][0];

    const int hidx = colg * 32 + r;    // epilogue threads only
    float hown = 0.f;

    for (int t = 0; t < Lg; ++t) {
        const bool act = (t < mylen);
        const float hstep = hown;

        float xr = 0.f, xz = 0.f, xl = 0.f, xc = 0.f, xw = 0.f;
        if (epi) {
            const float* xp = g_XP + ((size_t)(t * 5) * HDIM + colg) * BATCH + b;
            xr = __ldcg(xp + 0 * XP_MS);
            xz = __ldcg(xp + 1 * XP_MS);
            xl = __ldcg(xp + 2 * XP_MS);
            xc = __ldcg(xp + 3 * XP_MS);
            xw = __ldcg(xp + 4 * XP_MS);
        }

        // ================= phase A: 4 GEMMs, warp = k-slice ==================
        {
            const ull* rbuf = (p & 1) ? buf1 : buf0;
            float*     bank = Gp + (p & 1) * GPBANK;
            gemm_warp<4>(rbuf, Wsm, bank, w, lane, p);
            __syncthreads();
            if (epi) {
                float gr = 0.f, gz = 0.f, gl = 0.f, gch = 0.f;
                #pragma unroll
                for (int ww = 0; ww < 8; ++ww) {
                    const float* q = bank + ww * 512 + tid;
                    gr += q[0]; gz += q[128]; gl += q[256]; gch += q[384];
                }
                float rv = sigmoidf_(xr + gr);
                float zv = sigmoidf_(xz + gz);
                float lv = sigmoidf_(xl + gl);
                float nv = tanhf_(xc + rv * gch) + lv * xw;
                hown = (1.f - zv) * hown + zv * nv;
                ull pk;
                asm("mov.b64 %0,{%1,%2};" : "=l"(pk)
                    : "r"(__float_as_uint(hown)), "r"(p + 1));
                st_rlx64(((p & 1) ? buf0 : buf1) + hidx, pk);   // publish
            }
        }
        ++p;

        // ================= 4 transition layers (Tr,Tz,Tn) ===================
        #pragma unroll 1
        for (int layer = 0; layer < NLAYERS; ++layer) {
            const ull* rbuf = (p & 1) ? buf1 : buf0;
            float*     bank = Gp + (p & 1) * GPBANK;
            gemm_warp<3>(rbuf, Wsm + (4 + 3 * layer) * 1024, bank, w, lane, p);
            __syncthreads();
            if (epi) {
                float grr = 0.f, gzz = 0.f, gnn = 0.f;
                #pragma unroll
                for (int ww = 0; ww < 8; ++ww) {
                    const float* q = bank + ww * 512 + tid;
                    grr += q[0]; gzz += q[128]; gnn += q[256];
                }
                float rr = sigmoidf_(grr);
                float zz = sigmoidf_(gzz);
                float nn = tanhf_(rr * gnn);
                float hnew = (1.f - zz) * nn + zz * hown;

                float outval = 0.f;
                bool  dostore = false;
                if (layer == NLAYERS - 1) {
                    hown = act ? hnew : hstep;
                    outval  = hnew;
                    dostore = act;
                } else {
                    hown = hnew;
                }
                ull pk;
                asm("mov.b64 %0,{%1,%2};" : "=l"(pk)
                    : "r"(__float_as_uint(hown)), "r"(p + 1));
                st_rlx64(((p & 1) ? buf0 : buf1) + hidx, pk);   // publish first
                if (dostore)   // off the critical path
                    out[((size_t)t * BATCH + b) * HDIM + colg] = outval;
            }
            ++p;
        }
    }
}

// ---------------------------------------------------------------------------
// kernel_launch: memsets -> x-projection GEMM -> persistent recurrence
// ---------------------------------------------------------------------------
extern "C" void kernel_launch(void* const* d_in, const int* in_sizes, int n_in,
                              void* d_out, int out_size)
{
    const float* x       = (const float*)d_in[0];
    const int*   lengths = (const int*)  d_in[1];
    const float* Wr      = (const float*)d_in[2];
    const float* Wz      = (const float*)d_in[3];
    const float* Wl      = (const float*)d_in[4];
    const float* Wt      = (const float*)d_in[5];
    const float* Cx      = (const float*)d_in[6];
    const float* Ch      = (const float*)d_in[7];
    const float* Tr      = (const float*)d_in[8];
    const float* Tz      = (const float*)d_in[9];
    const float* Tn      = (const float*)d_in[10];
    float* out = (float*)d_out;
    (void)in_sizes; (void)n_in;

    cudaMemsetAsync(out, 0, (size_t)out_size * sizeof(float));

    // Ring buffer must start with {0.0f, tag=0} every launch. Graph-replay safe.
    void* hb_ptr = nullptr;
    cudaGetSymbolAddress(&hb_ptr, g_Hbuf);
    cudaMemsetAsync(hb_ptr, 0, sizeof(ull) * 2 * GROUPS * HDIM * RPG);

    dim3 ggrid(20, 1024);
    xproj_kernel<<<ggrid, 256>>>(x, Wr, Wz, Wl, Cx, Wt);

    cudaFuncSetAttribute(rnn_kernel,
                         cudaFuncAttributeMaxDynamicSharedMemorySize,
                         SMEM_BYTES);
    rnn_kernel<<<GROUPS * CPG, 256, SMEM_BYTES>>>(
        Wr, Wz, Wl, Ch, Tr, Tz, Tn, lengths, out);
}